// round 1
// baseline (speedup 1.0000x reference)
#include <cuda_runtime.h>

#define NN 100000
#define EE 1600000
#define FI 128
#define DD 32
#define GG 1000
#define CC 10
#define BN_EPS 1e-5f

// Scratch (device globals: no allocation allowed)
__device__ __align__(16) float g_p[NN * DD];     // projected features per node
__device__ __align__(16) float g_agg[NN * DD];   // edge-aggregated projections
__device__ __align__(16) float g_h[NN * DD];     // layer output (pre-BN)
__device__ float g_stats[5 * 2 * DD];            // per-BN-layer [sum(32), sumsq(32)]
__device__ float g_pooled[GG * DD];              // global_add_pool accumulator

// ---------------------------------------------------------------------------
__global__ void k_init() {
    int i = blockIdx.x * blockDim.x + threadIdx.x;
    if (i < GG * DD) g_pooled[i] = 0.f;
    if (i < 5 * 2 * DD) g_stats[i] = 0.f;
}

// ---------------------------------------------------------------------------
// Layer-1 projection: p = x @ W1a  (N x 128 @ 128 x 32), agg = 0
__global__ __launch_bounds__(256) void k_proj1(const float* __restrict__ x,
                                               const float* __restrict__ W) {
    __shared__ __align__(16) float sW[FI * DD];
    for (int i = threadIdx.x; i < FI * DD; i += 256) sW[i] = W[i];
    __syncthreads();

    int node = blockIdx.x * 256 + threadIdx.x;
    if (node >= NN) return;

    float acc[DD];
#pragma unroll
    for (int j = 0; j < DD; j++) acc[j] = 0.f;

    const float4* xr = (const float4*)(x + (size_t)node * FI);
#pragma unroll 4
    for (int k4 = 0; k4 < FI / 4; k4++) {
        float4 xv = xr[k4];
#pragma unroll
        for (int t = 0; t < 4; t++) {
            float xs = (t == 0) ? xv.x : (t == 1) ? xv.y : (t == 2) ? xv.z : xv.w;
            const float4* wr = (const float4*)&sW[(k4 * 4 + t) * DD];
#pragma unroll
            for (int j4 = 0; j4 < DD / 4; j4++) {
                float4 w = wr[j4];
                acc[j4 * 4 + 0] += xs * w.x;
                acc[j4 * 4 + 1] += xs * w.y;
                acc[j4 * 4 + 2] += xs * w.z;
                acc[j4 * 4 + 3] += xs * w.w;
            }
        }
    }
    float4* pp = (float4*)&g_p[(size_t)node * DD];
    float4* ag = (float4*)&g_agg[(size_t)node * DD];
#pragma unroll
    for (int j4 = 0; j4 < DD / 4; j4++) {
        pp[j4] = make_float4(acc[j4 * 4], acc[j4 * 4 + 1], acc[j4 * 4 + 2], acc[j4 * 4 + 3]);
        ag[j4] = make_float4(0.f, 0.f, 0.f, 0.f);
    }
}

// ---------------------------------------------------------------------------
// Layers 2-5 projection with folded BatchNorm:
//   bn(h) = s*h + c  (per-feature);  p = bn(h) @ Wa = h @ (diag(s)Wa) + c@Wa
__global__ __launch_bounds__(256) void k_proj(int stats_layer,
                                              const float* __restrict__ gamma,
                                              const float* __restrict__ beta,
                                              const float* __restrict__ Wa) {
    __shared__ float sS[DD], sC[DD], sCB[DD];
    __shared__ __align__(16) float sW[DD * DD];
    const float* st = g_stats + stats_layer * 2 * DD;
    if (threadIdx.x < DD) {
        float m = st[threadIdx.x] * (1.f / NN);
        float v = st[DD + threadIdx.x] * (1.f / NN) - m * m;
        float s = gamma[threadIdx.x] * rsqrtf(v + BN_EPS);
        sS[threadIdx.x] = s;
        sC[threadIdx.x] = beta[threadIdx.x] - m * s;
    }
    __syncthreads();
    for (int i = threadIdx.x; i < DD * DD; i += 256) sW[i] = sS[i >> 5] * Wa[i];
    __syncthreads();
    if (threadIdx.x < DD) {
        float c = 0.f;
#pragma unroll
        for (int f = 0; f < DD; f++) c += sC[f] * Wa[f * DD + threadIdx.x];
        sCB[threadIdx.x] = c;
    }
    __syncthreads();

    int node = blockIdx.x * 256 + threadIdx.x;
    if (node >= NN) return;

    float hv[DD];
    const float4* hr = (const float4*)&g_h[(size_t)node * DD];
#pragma unroll
    for (int j4 = 0; j4 < 8; j4++) {
        float4 t = hr[j4];
        hv[j4 * 4 + 0] = t.x; hv[j4 * 4 + 1] = t.y;
        hv[j4 * 4 + 2] = t.z; hv[j4 * 4 + 3] = t.w;
    }
    float acc[DD];
#pragma unroll
    for (int j = 0; j < DD; j++) acc[j] = sCB[j];
#pragma unroll 4
    for (int k = 0; k < DD; k++) {
        float hk = hv[k];
        const float4* wr = (const float4*)&sW[k * DD];
#pragma unroll
        for (int j4 = 0; j4 < 8; j4++) {
            float4 w = wr[j4];
            acc[j4 * 4 + 0] += hk * w.x;
            acc[j4 * 4 + 1] += hk * w.y;
            acc[j4 * 4 + 2] += hk * w.z;
            acc[j4 * 4 + 3] += hk * w.w;
        }
    }
    float4* pp = (float4*)&g_p[(size_t)node * DD];
    float4* ag = (float4*)&g_agg[(size_t)node * DD];
#pragma unroll
    for (int j4 = 0; j4 < 8; j4++) {
        pp[j4] = make_float4(acc[j4 * 4], acc[j4 * 4 + 1], acc[j4 * 4 + 2], acc[j4 * 4 + 3]);
        ag[j4] = make_float4(0.f, 0.f, 0.f, 0.f);
    }
}

// ---------------------------------------------------------------------------
// Edge scatter: agg[dst] += p[src]. 8 threads per edge, one float4 each.
__global__ __launch_bounds__(256) void k_scatter(const int* __restrict__ src,
                                                 const int* __restrict__ dst) {
    long long t = (long long)blockIdx.x * 256 + threadIdx.x;
    int e = (int)(t >> 3);
    int q = (int)(t & 7);
    if (e >= EE) return;
    int s = __ldg(&src[e]);
    int d = __ldg(&dst[e]);
    float4 v = ((const float4*)&g_p[(size_t)s * DD])[q];
    float* ad = &g_agg[(size_t)d * DD + q * 4];
    atomicAdd(ad + 0, v.x);
    atomicAdd(ad + 1, v.y);
    atomicAdd(ad + 2, v.z);
    atomicAdd(ad + 3, v.w);
}

// ---------------------------------------------------------------------------
// MLP: t = relu(p + agg + ba); h = relu(t @ Wb + bb)
__global__ __launch_bounds__(256) void k_mlp(const float* __restrict__ ba,
                                             const float* __restrict__ Wb,
                                             const float* __restrict__ bb) {
    __shared__ __align__(16) float sW[DD * DD];
    __shared__ float sba[DD], sbb[DD];
    for (int i = threadIdx.x; i < DD * DD; i += 256) sW[i] = Wb[i];
    if (threadIdx.x < DD) { sba[threadIdx.x] = ba[threadIdx.x]; sbb[threadIdx.x] = bb[threadIdx.x]; }
    __syncthreads();

    int node = blockIdx.x * 256 + threadIdx.x;
    if (node >= NN) return;

    float tt[DD];
    const float4* pp = (const float4*)&g_p[(size_t)node * DD];
    const float4* ag = (const float4*)&g_agg[(size_t)node * DD];
#pragma unroll
    for (int j4 = 0; j4 < 8; j4++) {
        float4 a = pp[j4], b = ag[j4];
        tt[j4 * 4 + 0] = fmaxf(a.x + b.x + sba[j4 * 4 + 0], 0.f);
        tt[j4 * 4 + 1] = fmaxf(a.y + b.y + sba[j4 * 4 + 1], 0.f);
        tt[j4 * 4 + 2] = fmaxf(a.z + b.z + sba[j4 * 4 + 2], 0.f);
        tt[j4 * 4 + 3] = fmaxf(a.w + b.w + sba[j4 * 4 + 3], 0.f);
    }
    float acc[DD];
#pragma unroll
    for (int j = 0; j < DD; j++) acc[j] = sbb[j];
#pragma unroll 4
    for (int k = 0; k < DD; k++) {
        float tk = tt[k];
        const float4* wr = (const float4*)&sW[k * DD];
#pragma unroll
        for (int j4 = 0; j4 < 8; j4++) {
            float4 w = wr[j4];
            acc[j4 * 4 + 0] += tk * w.x;
            acc[j4 * 4 + 1] += tk * w.y;
            acc[j4 * 4 + 2] += tk * w.z;
            acc[j4 * 4 + 3] += tk * w.w;
        }
    }
    float4* hh = (float4*)&g_h[(size_t)node * DD];
#pragma unroll
    for (int j4 = 0; j4 < 8; j4++) {
        hh[j4] = make_float4(fmaxf(acc[j4 * 4 + 0], 0.f), fmaxf(acc[j4 * 4 + 1], 0.f),
                             fmaxf(acc[j4 * 4 + 2], 0.f), fmaxf(acc[j4 * 4 + 3], 0.f));
    }
}

// ---------------------------------------------------------------------------
// Column sums / sum-of-squares of g_h for BatchNorm stats.
__global__ __launch_bounds__(256) void k_stats(int stats_layer) {
    int lane = threadIdx.x & 31;
    int w = threadIdx.x >> 5;
    int start = blockIdx.x * 512;
    int end = min(start + 512, NN);
    float s = 0.f, q = 0.f;
    for (int n = start + w; n < end; n += 8) {
        float v = g_h[(size_t)n * DD + lane];
        s += v;
        q += v * v;
    }
    __shared__ float ss[8][DD], sq[8][DD];
    ss[w][lane] = s;
    sq[w][lane] = q;
    __syncthreads();
    if (w == 0) {
#pragma unroll
        for (int i = 1; i < 8; i++) { s += ss[i][lane]; q += sq[i][lane]; }
        float* st = g_stats + stats_layer * 2 * DD;
        atomicAdd(&st[lane], s);
        atomicAdd(&st[DD + lane], q);
    }
}

// ---------------------------------------------------------------------------
// Global add pool of bn(h) over graphs. 32 threads per node (lane = feature).
__global__ __launch_bounds__(256) void k_pool(const int* __restrict__ batch,
                                              int stats_layer,
                                              const float* __restrict__ gamma,
                                              const float* __restrict__ beta) {
    __shared__ float sS[DD], sC[DD];
    const float* st = g_stats + stats_layer * 2 * DD;
    if (threadIdx.x < DD) {
        float m = st[threadIdx.x] * (1.f / NN);
        float v = st[DD + threadIdx.x] * (1.f / NN) - m * m;
        float s = gamma[threadIdx.x] * rsqrtf(v + BN_EPS);
        sS[threadIdx.x] = s;
        sC[threadIdx.x] = beta[threadIdx.x] - m * s;
    }
    __syncthreads();
    long long t = (long long)blockIdx.x * 256 + threadIdx.x;
    int node = (int)(t >> 5);
    int j = (int)(t & 31);
    if (node >= NN) return;
    int g = __ldg(&batch[node]);
    float v = sS[j] * g_h[(size_t)node * DD + j] + sC[j];
    atomicAdd(&g_pooled[g * DD + j], v);
}

// ---------------------------------------------------------------------------
// Head: relu(pooled@fc1+b1) @ fc2 + b2, log_softmax. One thread per graph.
__global__ __launch_bounds__(256) void k_head(const float* __restrict__ fc1w,
                                              const float* __restrict__ fc1b,
                                              const float* __restrict__ fc2w,
                                              const float* __restrict__ fc2b,
                                              float* __restrict__ out) {
    __shared__ float sW1[DD * DD], sW2[DD * CC], sb1[DD], sb2[CC];
    for (int i = threadIdx.x; i < DD * DD; i += 256) sW1[i] = fc1w[i];
    for (int i = threadIdx.x; i < DD * CC; i += 256) sW2[i] = fc2w[i];
    if (threadIdx.x < DD) sb1[threadIdx.x] = fc1b[threadIdx.x];
    if (threadIdx.x < CC) sb2[threadIdx.x] = fc2b[threadIdx.x];
    __syncthreads();

    int g = blockIdx.x * 256 + threadIdx.x;
    if (g >= GG) return;

    float pv[DD];
    const float4* pr = (const float4*)&g_pooled[g * DD];
#pragma unroll
    for (int j4 = 0; j4 < 8; j4++) {
        float4 t = pr[j4];
        pv[j4 * 4 + 0] = t.x; pv[j4 * 4 + 1] = t.y;
        pv[j4 * 4 + 2] = t.z; pv[j4 * 4 + 3] = t.w;
    }
    float u[DD];
#pragma unroll
    for (int j = 0; j < DD; j++) u[j] = sb1[j];
#pragma unroll 4
    for (int k = 0; k < DD; k++) {
        float pk = pv[k];
#pragma unroll
        for (int j = 0; j < DD; j++) u[j] += pk * sW1[k * DD + j];
    }
#pragma unroll
    for (int j = 0; j < DD; j++) u[j] = fmaxf(u[j], 0.f);

    float lg[CC];
#pragma unroll
    for (int c = 0; c < CC; c++) lg[c] = sb2[c];
#pragma unroll 4
    for (int j = 0; j < DD; j++) {
        float uj = u[j];
#pragma unroll
        for (int c = 0; c < CC; c++) lg[c] += uj * sW2[j * CC + c];
    }
    float mx = lg[0];
#pragma unroll
    for (int c = 1; c < CC; c++) mx = fmaxf(mx, lg[c]);
    float se = 0.f;
#pragma unroll
    for (int c = 0; c < CC; c++) se += expf(lg[c] - mx);
    float lse = mx + logf(se);
#pragma unroll
    for (int c = 0; c < CC; c++) out[g * CC + c] = lg[c] - lse;
}

// ---------------------------------------------------------------------------
extern "C" void kernel_launch(void* const* d_in, const int* in_sizes, int n_in,
                              void* d_out, int out_size) {
    const float* x     = (const float*)d_in[0];
    const int*   ei    = (const int*)d_in[1];
    const int*   batch = (const int*)d_in[2];
    const float* W1a   = (const float*)d_in[3];
    const float* b1a   = (const float*)d_in[4];
    const float* W1b   = (const float*)d_in[5];
    const float* b1b   = (const float*)d_in[6];
    const float* Wa    = (const float*)d_in[7];
    const float* ba    = (const float*)d_in[8];
    const float* Wb    = (const float*)d_in[9];
    const float* bb    = (const float*)d_in[10];
    const float* gamma = (const float*)d_in[11];
    const float* beta  = (const float*)d_in[12];
    const float* fc1w  = (const float*)d_in[13];
    const float* fc1b  = (const float*)d_in[14];
    const float* fc2w  = (const float*)d_in[15];
    const float* fc2b  = (const float*)d_in[16];
    float* out = (float*)d_out;

    const int* src = ei;        // row 0
    const int* dst = ei + EE;   // row 1

    const int NB = (NN + 255) / 256;               // 391
    const int SB = (EE * 8) / 256;                 // 50000
    const int STB = (NN + 511) / 512;              // 196

    k_init<<<(GG * DD + 255) / 256, 256>>>();

    // Layer 1 (GIN F->D->D, relu, BN stats)
    k_proj1<<<NB, 256>>>(x, W1a);
    k_scatter<<<SB, 256>>>(src, dst);
    k_mlp<<<NB, 256>>>(b1a, W1b, b1b);
    k_stats<<<STB, 256>>>(0);

    // Layers 2-5 (BN folded into projection)
    for (int i = 0; i < 4; i++) {
        k_proj<<<NB, 256>>>(i, gamma + i * DD, beta + i * DD, Wa + i * DD * DD);
        k_scatter<<<SB, 256>>>(src, dst);
        k_mlp<<<NB, 256>>>(ba + i * DD, Wb + i * DD * DD, bb + i * DD);
        k_stats<<<STB, 256>>>(i + 1);
    }

    // Pool (applies BN layer 5) + head
    k_pool<<<(NN * 32) / 256, 256>>>(batch, 4, gamma + 4 * DD, beta + 4 * DD);
    k_head<<<(GG + 255) / 256, 256>>>(fc1w, fc1b, fc2w, fc2b, out);
}

// round 2
// speedup vs baseline: 1.8637x; 1.8637x over previous
#include <cuda_runtime.h>

#define NN 100000
#define EE 1600000
#define FI 128
#define DD 32
#define GG 1000
#define CC 10
#define BN_EPS 1e-5f

// Scratch (device globals: no allocation allowed)
__device__ __align__(128) float g_p[NN * DD];   // projected features per node
__device__ __align__(128) float g_h[NN * DD];   // layer output (pre-BN)
__device__ float g_stats[5 * 2 * DD];           // per-BN-layer [sum(32), sumsq(32)]
__device__ float g_pooled[GG * DD];             // global_add_pool accumulator
__device__ int g_deg[NN];                       // in-degree
__device__ int g_row[NN];                       // CSR row offsets (exclusive scan of deg)
__device__ int g_pos[NN];                       // fill cursor
__device__ int g_csr[EE];                       // src ids sorted by dst
__device__ int g_bsum[128];                     // scan block sums
__device__ int g_boff[128];                     // scan block offsets

// ---------------------------------------------------------------------------
__global__ void k_init() {
    int i = blockIdx.x * blockDim.x + threadIdx.x;
    if (i < GG * DD) g_pooled[i] = 0.f;
    if (i < 5 * 2 * DD) g_stats[i] = 0.f;
    if (i < NN) g_deg[i] = 0;
}

// ---------------------------------------------------------------------------
// CSR build: degree histogram
__global__ __launch_bounds__(256) void k_hist(const int* __restrict__ dst) {
    int e = blockIdx.x * 256 + threadIdx.x;
    if (e < EE) atomicAdd(&g_deg[dst[e]], 1);
}

// Block-local exclusive scan (1024 elems/block) + block totals
__global__ __launch_bounds__(256) void k_scan1() {
    int b = blockIdx.x, t = threadIdx.x;
    int lane = t & 31, w = t >> 5;
    int idx0 = b * 1024 + t * 4;
    int v[4];
#pragma unroll
    for (int u = 0; u < 4; u++) v[u] = (idx0 + u < NN) ? g_deg[idx0 + u] : 0;
    int tsum = v[0] + v[1] + v[2] + v[3];
    int incl = tsum;
#pragma unroll
    for (int d = 1; d < 32; d <<= 1) {
        int o = __shfl_up_sync(0xffffffffu, incl, d);
        if (lane >= d) incl += o;
    }
    __shared__ int wsum[8];
    if (lane == 31) wsum[w] = incl;
    __syncthreads();
    int woff = 0;
    for (int i = 0; i < w; i++) woff += wsum[i];
    int run = woff + incl - tsum;
#pragma unroll
    for (int u = 0; u < 4; u++) {
        if (idx0 + u < NN) g_row[idx0 + u] = run;
        run += v[u];
    }
    if (t == 255) g_bsum[b] = woff + incl;
}

__global__ void k_scan2(int nblk) {
    if (threadIdx.x == 0) {
        int s = 0;
        for (int i = 0; i < nblk; i++) { g_boff[i] = s; s += g_bsum[i]; }
    }
}

__global__ __launch_bounds__(256) void k_scan3() {
    int i = blockIdx.x * 256 + threadIdx.x;
    if (i < NN) {
        int r = g_row[i] + g_boff[i >> 10];
        g_row[i] = r;
        g_pos[i] = r;
    }
}

__global__ __launch_bounds__(256) void k_fill(const int* __restrict__ src,
                                              const int* __restrict__ dst) {
    int e = blockIdx.x * 256 + threadIdx.x;
    if (e < EE) {
        int slot = atomicAdd(&g_pos[dst[e]], 1);
        g_csr[slot] = src[e];
    }
}

// ---------------------------------------------------------------------------
// Layer-1 projection: p = x @ W1a  (N x 128 @ 128 x 32)
__global__ __launch_bounds__(256) void k_proj1(const float* __restrict__ x,
                                               const float* __restrict__ W) {
    __shared__ __align__(16) float sW[FI * DD];
    for (int i = threadIdx.x; i < FI * DD; i += 256) sW[i] = W[i];
    __syncthreads();

    int node = blockIdx.x * 256 + threadIdx.x;
    if (node >= NN) return;

    float acc[DD];
#pragma unroll
    for (int j = 0; j < DD; j++) acc[j] = 0.f;

    const float4* xr = (const float4*)(x + (size_t)node * FI);
#pragma unroll 4
    for (int k4 = 0; k4 < FI / 4; k4++) {
        float4 xv = xr[k4];
#pragma unroll
        for (int t = 0; t < 4; t++) {
            float xs = (t == 0) ? xv.x : (t == 1) ? xv.y : (t == 2) ? xv.z : xv.w;
            const float4* wr = (const float4*)&sW[(k4 * 4 + t) * DD];
#pragma unroll
            for (int j4 = 0; j4 < DD / 4; j4++) {
                float4 w = wr[j4];
                acc[j4 * 4 + 0] += xs * w.x;
                acc[j4 * 4 + 1] += xs * w.y;
                acc[j4 * 4 + 2] += xs * w.z;
                acc[j4 * 4 + 3] += xs * w.w;
            }
        }
    }
    float4* pp = (float4*)&g_p[(size_t)node * DD];
#pragma unroll
    for (int j4 = 0; j4 < DD / 4; j4++)
        pp[j4] = make_float4(acc[j4 * 4], acc[j4 * 4 + 1], acc[j4 * 4 + 2], acc[j4 * 4 + 3]);
}

// ---------------------------------------------------------------------------
// Layers 2-5 projection with folded BatchNorm:
//   bn(h) = s*h + c;  p = h @ (diag(s)Wa) + c@Wa
__global__ __launch_bounds__(256) void k_proj(int stats_layer,
                                              const float* __restrict__ gamma,
                                              const float* __restrict__ beta,
                                              const float* __restrict__ Wa) {
    __shared__ float sS[DD], sC[DD], sCB[DD];
    __shared__ __align__(16) float sW[DD * DD];
    const float* st = g_stats + stats_layer * 2 * DD;
    if (threadIdx.x < DD) {
        float m = st[threadIdx.x] * (1.f / NN);
        float v = st[DD + threadIdx.x] * (1.f / NN) - m * m;
        float s = gamma[threadIdx.x] * rsqrtf(v + BN_EPS);
        sS[threadIdx.x] = s;
        sC[threadIdx.x] = beta[threadIdx.x] - m * s;
    }
    __syncthreads();
    for (int i = threadIdx.x; i < DD * DD; i += 256) sW[i] = sS[i >> 5] * Wa[i];
    __syncthreads();
    if (threadIdx.x < DD) {
        float c = 0.f;
#pragma unroll
        for (int f = 0; f < DD; f++) c += sC[f] * Wa[f * DD + threadIdx.x];
        sCB[threadIdx.x] = c;
    }
    __syncthreads();

    int node = blockIdx.x * 256 + threadIdx.x;
    if (node >= NN) return;

    float hv[DD];
    const float4* hr = (const float4*)&g_h[(size_t)node * DD];
#pragma unroll
    for (int j4 = 0; j4 < 8; j4++) {
        float4 t = hr[j4];
        hv[j4 * 4 + 0] = t.x; hv[j4 * 4 + 1] = t.y;
        hv[j4 * 4 + 2] = t.z; hv[j4 * 4 + 3] = t.w;
    }
    float acc[DD];
#pragma unroll
    for (int j = 0; j < DD; j++) acc[j] = sCB[j];
#pragma unroll 4
    for (int k = 0; k < DD; k++) {
        float hk = hv[k];
        const float4* wr = (const float4*)&sW[k * DD];
#pragma unroll
        for (int j4 = 0; j4 < 8; j4++) {
            float4 w = wr[j4];
            acc[j4 * 4 + 0] += hk * w.x;
            acc[j4 * 4 + 1] += hk * w.y;
            acc[j4 * 4 + 2] += hk * w.z;
            acc[j4 * 4 + 3] += hk * w.w;
        }
    }
    float4* pp = (float4*)&g_p[(size_t)node * DD];
#pragma unroll
    for (int j4 = 0; j4 < 8; j4++)
        pp[j4] = make_float4(acc[j4 * 4], acc[j4 * 4 + 1], acc[j4 * 4 + 2], acc[j4 * 4 + 3]);
}

// ---------------------------------------------------------------------------
// Fused gather + MLP + stats. One warp per node, lane = feature.
//   agg = sum_{e in CSR[n]} p[src_e]   (coalesced 128B loads, no atomics)
//   t = relu(p[n] + agg + ba); h = relu(t @ Wb + bb); accumulate BN stats.
__global__ __launch_bounds__(256) void k_gma(const float* __restrict__ ba,
                                             const float* __restrict__ Wb,
                                             const float* __restrict__ bb,
                                             int stats_layer) {
    __shared__ __align__(16) float sW[DD * DD];
    __shared__ float sba[DD], sbb[DD], sS[DD], sQ[DD];
    for (int i = threadIdx.x; i < DD * DD; i += 256) sW[i] = Wb[i];
    if (threadIdx.x < DD) {
        sba[threadIdx.x] = ba[threadIdx.x];
        sbb[threadIdx.x] = bb[threadIdx.x];
        sS[threadIdx.x] = 0.f;
        sQ[threadIdx.x] = 0.f;
    }
    __syncthreads();

    int lane = threadIdx.x & 31;
    int w = threadIdx.x >> 5;
    int warpsTotal = gridDim.x * 8;
    float ls = 0.f, lq = 0.f;

    for (int n = blockIdx.x * 8 + w; n < NN; n += warpsTotal) {
        int base = g_row[n];
        int cnt = g_deg[n];
        float acc = 0.f;
        int i = 0;
        for (; i + 4 <= cnt; i += 4) {
            int s0 = g_csr[base + i + 0];
            int s1 = g_csr[base + i + 1];
            int s2 = g_csr[base + i + 2];
            int s3 = g_csr[base + i + 3];
            float v0 = g_p[(size_t)s0 * DD + lane];
            float v1 = g_p[(size_t)s1 * DD + lane];
            float v2 = g_p[(size_t)s2 * DD + lane];
            float v3 = g_p[(size_t)s3 * DD + lane];
            acc += (v0 + v1) + (v2 + v3);
        }
        for (; i < cnt; i++) acc += g_p[(size_t)g_csr[base + i] * DD + lane];

        float t0 = fmaxf(g_p[(size_t)n * DD + lane] + acc + sba[lane], 0.f);
        float hv = sbb[lane];
#pragma unroll
        for (int k = 0; k < DD; k++) {
            float tk = __shfl_sync(0xffffffffu, t0, k);
            hv = fmaf(tk, sW[k * DD + lane], hv);
        }
        hv = fmaxf(hv, 0.f);
        g_h[(size_t)n * DD + lane] = hv;
        ls += hv;
        lq += hv * hv;
    }

    atomicAdd(&sS[lane], ls);
    atomicAdd(&sQ[lane], lq);
    __syncthreads();
    if (w == 0) {
        float* st = g_stats + stats_layer * 2 * DD;
        atomicAdd(&st[lane], sS[lane]);
        atomicAdd(&st[DD + lane], sQ[lane]);
    }
}

// ---------------------------------------------------------------------------
// Global add pool of bn(h) over graphs. 32 threads per node (lane = feature).
__global__ __launch_bounds__(256) void k_pool(const int* __restrict__ batch,
                                              int stats_layer,
                                              const float* __restrict__ gamma,
                                              const float* __restrict__ beta) {
    __shared__ float sS[DD], sC[DD];
    const float* st = g_stats + stats_layer * 2 * DD;
    if (threadIdx.x < DD) {
        float m = st[threadIdx.x] * (1.f / NN);
        float v = st[DD + threadIdx.x] * (1.f / NN) - m * m;
        float s = gamma[threadIdx.x] * rsqrtf(v + BN_EPS);
        sS[threadIdx.x] = s;
        sC[threadIdx.x] = beta[threadIdx.x] - m * s;
    }
    __syncthreads();
    long long t = (long long)blockIdx.x * 256 + threadIdx.x;
    int node = (int)(t >> 5);
    int j = (int)(t & 31);
    if (node >= NN) return;
    int g = __ldg(&batch[node]);
    float v = sS[j] * g_h[(size_t)node * DD + j] + sC[j];
    atomicAdd(&g_pooled[g * DD + j], v);
}

// ---------------------------------------------------------------------------
// Head: relu(pooled@fc1+b1) @ fc2 + b2, log_softmax. One thread per graph.
__global__ __launch_bounds__(256) void k_head(const float* __restrict__ fc1w,
                                              const float* __restrict__ fc1b,
                                              const float* __restrict__ fc2w,
                                              const float* __restrict__ fc2b,
                                              float* __restrict__ out) {
    __shared__ float sW1[DD * DD], sW2[DD * CC], sb1[DD], sb2[CC];
    for (int i = threadIdx.x; i < DD * DD; i += 256) sW1[i] = fc1w[i];
    for (int i = threadIdx.x; i < DD * CC; i += 256) sW2[i] = fc2w[i];
    if (threadIdx.x < DD) sb1[threadIdx.x] = fc1b[threadIdx.x];
    if (threadIdx.x < CC) sb2[threadIdx.x] = fc2b[threadIdx.x];
    __syncthreads();

    int g = blockIdx.x * 256 + threadIdx.x;
    if (g >= GG) return;

    float pv[DD];
    const float4* pr = (const float4*)&g_pooled[g * DD];
#pragma unroll
    for (int j4 = 0; j4 < 8; j4++) {
        float4 t = pr[j4];
        pv[j4 * 4 + 0] = t.x; pv[j4 * 4 + 1] = t.y;
        pv[j4 * 4 + 2] = t.z; pv[j4 * 4 + 3] = t.w;
    }
    float u[DD];
#pragma unroll
    for (int j = 0; j < DD; j++) u[j] = sb1[j];
#pragma unroll 4
    for (int k = 0; k < DD; k++) {
        float pk = pv[k];
#pragma unroll
        for (int j = 0; j < DD; j++) u[j] += pk * sW1[k * DD + j];
    }
#pragma unroll
    for (int j = 0; j < DD; j++) u[j] = fmaxf(u[j], 0.f);

    float lg[CC];
#pragma unroll
    for (int c = 0; c < CC; c++) lg[c] = sb2[c];
#pragma unroll 4
    for (int j = 0; j < DD; j++) {
        float uj = u[j];
#pragma unroll
        for (int c = 0; c < CC; c++) lg[c] += uj * sW2[j * CC + c];
    }
    float mx = lg[0];
#pragma unroll
    for (int c = 1; c < CC; c++) mx = fmaxf(mx, lg[c]);
    float se = 0.f;
#pragma unroll
    for (int c = 0; c < CC; c++) se += expf(lg[c] - mx);
    float lse = mx + logf(se);
#pragma unroll
    for (int c = 0; c < CC; c++) out[g * CC + c] = lg[c] - lse;
}

// ---------------------------------------------------------------------------
extern "C" void kernel_launch(void* const* d_in, const int* in_sizes, int n_in,
                              void* d_out, int out_size) {
    const float* x     = (const float*)d_in[0];
    const int*   ei    = (const int*)d_in[1];
    const int*   batch = (const int*)d_in[2];
    const float* W1a   = (const float*)d_in[3];
    const float* b1a   = (const float*)d_in[4];
    const float* W1b   = (const float*)d_in[5];
    const float* b1b   = (const float*)d_in[6];
    const float* Wa    = (const float*)d_in[7];
    const float* ba    = (const float*)d_in[8];
    const float* Wb    = (const float*)d_in[9];
    const float* bb    = (const float*)d_in[10];
    const float* gamma = (const float*)d_in[11];
    const float* beta  = (const float*)d_in[12];
    const float* fc1w  = (const float*)d_in[13];
    const float* fc1b  = (const float*)d_in[14];
    const float* fc2w  = (const float*)d_in[15];
    const float* fc2b  = (const float*)d_in[16];
    float* out = (float*)d_out;

    const int* src = ei;        // row 0
    const int* dst = ei + EE;   // row 1

    const int NB = (NN + 255) / 256;     // 391
    const int EB = EE / 256;             // 6250
    const int SCAN_BLK = (NN + 1023) / 1024;  // 98
    const int GMA_BLK = 1480;

    k_init<<<NB, 256>>>();

    // CSR build (dst-sorted edge list)
    k_hist<<<EB, 256>>>(dst);
    k_scan1<<<SCAN_BLK, 256>>>();
    k_scan2<<<1, 32>>>(SCAN_BLK);
    k_scan3<<<NB, 256>>>();
    k_fill<<<EB, 256>>>(src, dst);

    // Layer 1 (GIN F->D->D, relu; stats for BN 0)
    k_proj1<<<NB, 256>>>(x, W1a);
    k_gma<<<GMA_BLK, 256>>>(b1a, W1b, b1b, 0);

    // Layers 2-5 (BN folded into projection)
    for (int i = 0; i < 4; i++) {
        k_proj<<<NB, 256>>>(i, gamma + i * DD, beta + i * DD, Wa + i * DD * DD);
        k_gma<<<GMA_BLK, 256>>>(ba + i * DD, Wb + i * DD * DD, bb + i * DD, i + 1);
    }

    // Pool (applies BN layer 5) + head
    k_pool<<<(NN * 32 + 255) / 256, 256>>>(batch, 4, gamma + 4 * DD, beta + 4 * DD);
    k_head<<<(GG + 255) / 256, 256>>>(fc1w, fc1b, fc2w, fc2b, out);
}